// round 2
// baseline (speedup 1.0000x reference)
#include <cuda_runtime.h>
#include <cstdint>

// ScalarRoPEEmbedding:
//   positions:      int32 [8, 8192]              (d_in[0])  (JAX x64 off -> int32)
//   sin_cos_cache:  fp32  [10000, 256, 2]        (d_in[1])  row = 2048 B
//   out:            fp32  [8, 8192, 512]
// out[p, 2k] = cache[pos, k, 1] (cos); out[p, 2k+1] = cache[pos, k, 0] (sin)
// => output row = cache row with each (sin,cos) float pair swapped.

static constexpr int ROW_FLOATS = 512;          // EMBED_DIM
static constexpr int ROW_VEC4   = ROW_FLOATS/4; // 128 float4 per row
static constexpr int N_ROWS     = 8 * 8192;     // 65536
static constexpr long long TOTAL_VEC4 = (long long)N_ROWS * ROW_VEC4; // 8,388,608

__global__ void __launch_bounds__(256)
rope_gather_kernel(const int* __restrict__ positions,
                   const float4* __restrict__ cache,   // rows of 128 float4
                   float4* __restrict__ out)
{
    long long idx = (long long)blockIdx.x * blockDim.x + threadIdx.x;
    if (idx >= TOTAL_VEC4) return;

    int row = (int)(idx >> 7);       // which (batch, seq) position
    int col = (int)(idx & 127);      // which float4 within the 512-dim row

    long long pos = (long long)positions[row];  // broadcast within a row

    float4 v = cache[pos * ROW_VEC4 + col];  // (sin0, cos0, sin1, cos1)
    float4 o;
    o.x = v.y;   // cos0
    o.y = v.x;   // sin0
    o.z = v.w;   // cos1
    o.w = v.z;   // sin1

    out[idx] = o;
}

extern "C" void kernel_launch(void* const* d_in, const int* in_sizes, int n_in,
                              void* d_out, int out_size)
{
    const int*    positions = (const int*)d_in[0];
    const float4* cache     = (const float4*)d_in[1];
    float4*       out       = (float4*)d_out;

    const int threads = 256;
    const long long blocks = (TOTAL_VEC4 + threads - 1) / threads; // 32768
    rope_gather_kernel<<<(unsigned)blocks, threads>>>(positions, cache, out);
}

// round 3
// speedup vs baseline: 1.5097x; 1.5097x over previous
#include <cuda_runtime.h>
#include <cstdint>

// ScalarRoPEEmbedding:
//   positions:      int32 [8, 8192]
//   sin_cos_cache:  fp32  [10000, 256, 2]   row = 512 floats = 128 float4
//   out:            fp32  [8, 8192, 512]
// out row = cache row with each (sin,cos) float pair swapped.
//
// Layout: one warp handles TWO output rows. Each lane gathers 8 independent
// float4 (4 per row, warp-stride 32), front-batched for MLP=8, swaps pairs
// in registers, and writes with streaming stores (the 134MB output should
// not evict the 20MB cache from L2).

static constexpr int ROW_VEC4 = 128;     // float4 per 512-dim row
static constexpr int N_ROWS   = 8 * 8192;
static constexpr int ROWS_PER_WARP = 2;
static constexpr int THREADS  = 256;
static constexpr int WARPS_PER_BLOCK = THREADS / 32;

__device__ __forceinline__ float4 swap_pairs(float4 v) {
    float4 o;
    o.x = v.y; o.y = v.x; o.z = v.w; o.w = v.z;
    return o;
}

__device__ __forceinline__ void stcs(float4* p, float4 v) {
    asm volatile("st.global.cs.v4.f32 [%0], {%1,%2,%3,%4};"
                 :: "l"(p), "f"(v.x), "f"(v.y), "f"(v.z), "f"(v.w) : "memory");
}

__global__ void __launch_bounds__(THREADS)
rope_gather_kernel(const int* __restrict__ positions,
                   const float4* __restrict__ cache,
                   float4* __restrict__ out)
{
    const int warp_global = blockIdx.x * WARPS_PER_BLOCK + (threadIdx.x >> 5);
    const int lane        = threadIdx.x & 31;

    const int row0 = warp_global * ROWS_PER_WARP;   // first of 2 rows
    const int row1 = row0 + 1;
    // N_ROWS divisible by ROWS_PER_WARP*WARPS_PER_BLOCK; grid sized exactly.

    const int pos0 = positions[row0];               // warp-broadcast (same addr)
    const int pos1 = positions[row1];

    const float4* __restrict__ src0 = cache + (long long)pos0 * ROW_VEC4;
    const float4* __restrict__ src1 = cache + (long long)pos1 * ROW_VEC4;
    float4* __restrict__ dst0 = out + (long long)row0 * ROW_VEC4;
    float4* __restrict__ dst1 = out + (long long)row1 * ROW_VEC4;

    // Front-batch 8 independent gathers (MLP=8)
    float4 a0 = __ldg(src0 + lane);
    float4 a1 = __ldg(src0 + lane + 32);
    float4 a2 = __ldg(src0 + lane + 64);
    float4 a3 = __ldg(src0 + lane + 96);
    float4 b0 = __ldg(src1 + lane);
    float4 b1 = __ldg(src1 + lane + 32);
    float4 b2 = __ldg(src1 + lane + 64);
    float4 b3 = __ldg(src1 + lane + 96);

    stcs(dst0 + lane,      swap_pairs(a0));
    stcs(dst0 + lane + 32, swap_pairs(a1));
    stcs(dst0 + lane + 64, swap_pairs(a2));
    stcs(dst0 + lane + 96, swap_pairs(a3));
    stcs(dst1 + lane,      swap_pairs(b0));
    stcs(dst1 + lane + 32, swap_pairs(b1));
    stcs(dst1 + lane + 64, swap_pairs(b2));
    stcs(dst1 + lane + 96, swap_pairs(b3));
}

extern "C" void kernel_launch(void* const* d_in, const int* in_sizes, int n_in,
                              void* d_out, int out_size)
{
    const int*    positions = (const int*)d_in[0];
    const float4* cache     = (const float4*)d_in[1];
    float4*       out       = (float4*)d_out;

    const int rows_per_block = ROWS_PER_WARP * WARPS_PER_BLOCK;  // 16
    const int blocks = N_ROWS / rows_per_block;                  // 4096
    rope_gather_kernel<<<blocks, THREADS>>>(positions, cache, out);
}